// round 10
// baseline (speedup 1.0000x reference)
#include <cuda_runtime.h>
#include <cuda_fp16.h>
#include <cstdint>

#define SEQ 2048
#define NB  32
#define DIM 128
#define NTOK (NB*SEQ)
#define TOK 128
#define NTILES (NTOK/TOK)      // 512
#define GRID 256               // 2 tiles per CTA, 2 CTAs/SM

// ---------------- scratch (no allocations allowed) ----------------
__device__ __align__(16) __half g_h0[NTOK*DIM];
__device__ __align__(16) __half g_h1[NTOK*DIM];
__device__ float g_part[NB*DIM];
// prepared weight images: fp16 hi / scaled-lo(x1024), [n][k], swizzle baked
__device__ __align__(16) __half g_Whi[4][DIM*DIM];
__device__ __align__(16) __half g_Wlo[4][DIM*DIM];

// ---------------- helpers ----------------
__device__ __forceinline__ uint32_t smem_u32(const void* p) {
    uint32_t a;
    asm("{ .reg .u64 t; cvta.to.shared.u64 t, %1; cvt.u32.u64 %0, t; }" : "=r"(a) : "l"(p));
    return a;
}
__device__ __forceinline__ void sts128(uint32_t addr, uint4 v) {
    asm volatile("st.shared.v4.b32 [%0], {%1,%2,%3,%4};" :: "r"(addr), "r"(v.x), "r"(v.y), "r"(v.z), "r"(v.w) : "memory");
}
__device__ __forceinline__ void cpasync16(uint32_t dst, const void* src) {
    asm volatile("cp.async.cg.shared.global [%0], [%1], 16;" :: "r"(dst), "l"(src) : "memory");
}
#define CP_COMMIT() asm volatile("cp.async.commit_group;" ::: "memory")
#define CP_WAIT0()  asm volatile("cp.async.wait_group 0;" ::: "memory")
#define LDMX4(r, addr) \
    asm volatile("ldmatrix.sync.aligned.m8n8.x4.shared.b16 {%0,%1,%2,%3}, [%4];" \
        : "=r"((r)[0]), "=r"((r)[1]), "=r"((r)[2]), "=r"((r)[3]) : "r"(addr))
__device__ __forceinline__ void mma16816(float* d, const uint32_t* a, const uint32_t* b) {
    asm volatile(
        "mma.sync.aligned.m16n8k16.row.col.f32.f16.f16.f32 "
        "{%0,%1,%2,%3}, {%4,%5,%6,%7}, {%8,%9}, {%0,%1,%2,%3};"
        : "+f"(d[0]), "+f"(d[1]), "+f"(d[2]), "+f"(d[3])
        : "r"(a[0]), "r"(a[1]), "r"(a[2]), "r"(a[3]), "r"(b[0]), "r"(b[1]));
}
// swizzled byte offset inside a [rows][128 fp16] tile: 256B rows, 16B chunks
__device__ __forceinline__ uint32_t tswz(int row, int kchunk) {
    return (uint32_t)(row * 256 + ((kchunk ^ (row & 7)) << 4));
}
__device__ __forceinline__ uint32_t packh(float a, float b) {
    __half2 t = __floats2half2_rn(a, b);
    return *reinterpret_cast<uint32_t*>(&t);
}
__device__ __forceinline__ uint4 ldg128(const void* p) {
    uint4 v;
    asm volatile("ld.global.nc.v4.b32 {%0,%1,%2,%3}, [%4];"
        : "=r"(v.x), "=r"(v.y), "=r"(v.z), "=r"(v.w) : "l"(p));
    return v;
}

// ---------------------------------------------------------------------------
// Weight prep (+ zero pool partials): fp32 [k][n] -> fp16 hi + lo*2^10, [n][k]
// ---------------------------------------------------------------------------
__global__ void prep_w(const float* __restrict__ w0, const float* __restrict__ w1,
                       const float* __restrict__ w2, const float* __restrict__ w3)
{
    const float* ws[4] = {w0, w1, w2, w3};
    const float* w = ws[blockIdx.x];
    __half* bh = g_Whi[blockIdx.x];
    __half* bl = g_Wlo[blockIdx.x];
    if (blockIdx.x == 0) {
        for (int i = threadIdx.x; i < NB * DIM; i += blockDim.x) g_part[i] = 0.f;
    }
    for (int c = threadIdx.x; c < 2048; c += blockDim.x) {
        const int n = c >> 4, kc = c & 15, k0 = kc * 8;
        const int base = n * 128 + ((kc ^ (n & 7)) << 3);
        #pragma unroll
        for (int j = 0; j < 8; j++) {
            const float v = w[(k0 + j) * DIM + n];
            const __half hi = __float2half_rn(v);
            bh[base + j] = hi;
            bl[base + j] = __float2half_rn((v - __half2float(hi)) * 1024.0f);
        }
    }
}

// ---------------------------------------------------------------------------
// Persistent stage kernel: TOK=128 tile, 2 CTAs/SM (regs<=128 via folded acc).
// Build does band_agg directly from GMEM (L2-hot) in half2 math.
// mode 0 = encoder, mode 1 = gc (store), mode 2 = gc + fused mean-pool
// ---------------------------------------------------------------------------
__global__ __launch_bounds__(256, 2)
void stage_kernel(const void* __restrict__ in_v,
                  const __half* __restrict__ Whi_g,
                  const __half* __restrict__ Wlo_g,
                  const float* __restrict__ bias,
                  const float* __restrict__ w1, const float* __restrict__ b1,
                  __half* __restrict__ out, int mode)
{
    extern __shared__ float sm[];
    const int tid = threadIdx.x;
    const int wid = tid >> 5, lid = tid & 31;
    const uint32_t smb = smem_u32(sm);
    const uint32_t AS  = smb + 4096;       // 32KB (128 x 256B)
    const uint32_t BhS = AS + 32768;       // 32KB
    const uint32_t BlS = BhS + 32768;      // 32KB  -> total 100KB

    // ---- prologue: B hi/lo images + header ----
    {
        const char* sh = (const char*)Whi_g;
        const char* sl = (const char*)Wlo_g;
        #pragma unroll
        for (int it = 0; it < 8; it++) {
            const int i = tid + it * 256;
            cpasync16(BhS + i * 16, sh + i * 16);
            cpasync16(BlS + i * 16, sl + i * 16);
        }
        CP_COMMIT();
    }
    if (tid < 128) sm[tid] = bias[tid];
    if (mode == 0) {
        for (int i = tid; i < 768; i += 256) sm[128 + i] = w1[i];
        if (tid < 128) sm[896 + tid] = b1[tid];
    }
    CP_WAIT0();
    __syncthreads();

    const int r = tid >> 1, q = tid & 1;           // build: 2 threads/row
    const int wm = wid & 1, wn = wid >> 1;         // warp grid 2m x 4n
    const int g = lid >> 2, t4 = lid & 3;
    const int arowl = ((lid >> 3) & 1) * 8 + (lid & 7);
    const int akcl  = lid >> 4;
    const int browl = (lid >> 4) * 8 + (lid & 7);
    const int bkcl  = (lid >> 3) & 1;

    for (int tile = blockIdx.x; tile < NTILES; tile += GRID) {
        const int token0 = tile * TOK;

        // ---- build A fp16 tile (128 x 128), swizzled ----
        if (mode != 0) {
            const __half* hin = (const __half*)in_v;
            const int s = (token0 & (SEQ - 1)) + r;
            const float scf = (s == 0 || s == SEQ - 1) ? 0.5f : (1.0f / 3.0f);
            const __half2 sc = __float2half2_rn(scf);
            const char* rowc = (const char*)(hin + (size_t)(token0 + r) * DIM);
            const bool hl = (s > 0), hr = (s < SEQ - 1);
            #pragma unroll
            for (int ch = 0; ch < 8; ch++) {
                const int c = q * 8 + ch;
                const uint4 u1 = ldg128(rowc + c * 16);
                uint4 u0 = make_uint4(0, 0, 0, 0), u2 = u0;
                if (hl) u0 = ldg128(rowc - 256 + c * 16);
                if (hr) u2 = ldg128(rowc + 256 + c * 16);
                uint4 o;
                const uint32_t* p0 = &u0.x;
                const uint32_t* p1 = &u1.x;
                const uint32_t* p2 = &u2.x;
                uint32_t* po = &o.x;
                #pragma unroll
                for (int wd = 0; wd < 4; wd++) {
                    __half2 a = *(const __half2*)&p0[wd];
                    __half2 b = *(const __half2*)&p1[wd];
                    __half2 cc = *(const __half2*)&p2[wd];
                    __half2 sv = __hmul2(__hadd2(__hadd2(a, b), cc), sc);
                    po[wd] = *reinterpret_cast<uint32_t*>(&sv);
                }
                sts128(AS + tswz(r, c), o);
            }
        } else {
            const float* x = (const float*)in_v;
            float xv[6];
            const float* xr = x + (size_t)(token0 + r) * 6;
            #pragma unroll
            for (int k = 0; k < 6; k++) xv[k] = xr[k];
            #pragma unroll
            for (int ch = 0; ch < 8; ch++) {
                const int c = q * 8 + ch;
                const int k0 = c * 8;
                uint4 o;
                uint32_t* po = &o.x;
                #pragma unroll
                for (int wd = 0; wd < 4; wd++) {
                    float v0, v1;
                    {
                        const int cc = k0 + wd * 2;
                        float a = sm[896 + cc];
                        #pragma unroll
                        for (int k = 0; k < 6; k++) a += xv[k] * sm[128 + k * 128 + cc];
                        v0 = fmaxf(a, 0.f);
                    }
                    {
                        const int cc = k0 + wd * 2 + 1;
                        float a = sm[896 + cc];
                        #pragma unroll
                        for (int k = 0; k < 6; k++) a += xv[k] * sm[128 + k * 128 + cc];
                        v1 = fmaxf(a, 0.f);
                    }
                    po[wd] = packh(v0, v1);
                }
                sts128(AS + tswz(r, c), o);
            }
        }
        __syncthreads();   // A ready

        // ---- folded 2-pass GEMM: acc = (A@Wlo)/1024 + A@Whi ----
        float acc[4][4][4];
        #pragma unroll
        for (int mi = 0; mi < 4; mi++)
            #pragma unroll
            for (int ni = 0; ni < 4; ni++)
                #pragma unroll
                for (int j = 0; j < 4; j++) acc[mi][ni][j] = 0.f;

        // pass 1: lo
        #pragma unroll
        for (int ks = 0; ks < 8; ks++) {
            uint32_t ah[4][4];
            #pragma unroll
            for (int mi = 0; mi < 4; mi++)
                LDMX4(ah[mi], AS + tswz(wm * 64 + mi * 16 + arowl, ks * 2 + akcl));
            #pragma unroll
            for (int p = 0; p < 2; p++) {
                uint32_t bf[4];
                LDMX4(bf, BlS + tswz(wn * 32 + p * 16 + browl, ks * 2 + bkcl));
                #pragma unroll
                for (int hn = 0; hn < 2; hn++)
                    #pragma unroll
                    for (int mi = 0; mi < 4; mi++)
                        mma16816(acc[mi][p * 2 + hn], ah[mi], &bf[hn * 2]);
            }
        }
        // scale lo contribution
        #pragma unroll
        for (int mi = 0; mi < 4; mi++)
            #pragma unroll
            for (int ni = 0; ni < 4; ni++)
                #pragma unroll
                for (int j = 0; j < 4; j++) acc[mi][ni][j] *= (1.0f / 1024.0f);
        // pass 2: hi
        #pragma unroll
        for (int ks = 0; ks < 8; ks++) {
            uint32_t ah[4][4];
            #pragma unroll
            for (int mi = 0; mi < 4; mi++)
                LDMX4(ah[mi], AS + tswz(wm * 64 + mi * 16 + arowl, ks * 2 + akcl));
            #pragma unroll
            for (int p = 0; p < 2; p++) {
                uint32_t bf[4];
                LDMX4(bf, BhS + tswz(wn * 32 + p * 16 + browl, ks * 2 + bkcl));
                #pragma unroll
                for (int hn = 0; hn < 2; hn++)
                    #pragma unroll
                    for (int mi = 0; mi < 4; mi++)
                        mma16816(acc[mi][p * 2 + hn], ah[mi], &bf[hn * 2]);
            }
        }

        // ---- epilogue ----
        if (mode == 2) {
            const int b = token0 >> 11;
            #pragma unroll
            for (int ni = 0; ni < 4; ni++) {
                const int col = wn * 32 + ni * 8 + 2 * t4;
                const float bx = sm[col], by = sm[col + 1];
                float sx = 0.f, sy = 0.f;
                #pragma unroll
                for (int mi = 0; mi < 4; mi++) {
                    sx += fmaxf(acc[mi][ni][0] + bx, 0.f) + fmaxf(acc[mi][ni][2] + bx, 0.f);
                    sy += fmaxf(acc[mi][ni][1] + by, 0.f) + fmaxf(acc[mi][ni][3] + by, 0.f);
                }
                sx += __shfl_xor_sync(0xFFFFFFFFu, sx, 16);
                sy += __shfl_xor_sync(0xFFFFFFFFu, sy, 16);
                sx += __shfl_xor_sync(0xFFFFFFFFu, sx, 8);
                sy += __shfl_xor_sync(0xFFFFFFFFu, sy, 8);
                sx += __shfl_xor_sync(0xFFFFFFFFu, sx, 4);
                sy += __shfl_xor_sync(0xFFFFFFFFu, sy, 4);
                if (g == 0) {
                    atomicAdd(&g_part[b * DIM + col], sx);
                    atomicAdd(&g_part[b * DIM + col + 1], sy);
                }
            }
        } else {
            const bool relu = (mode == 1);
            #pragma unroll
            for (int mi = 0; mi < 4; mi++) {
                const int r0 = token0 + wm * 64 + mi * 16 + g;
                #pragma unroll
                for (int ni = 0; ni < 4; ni++) {
                    const int col = wn * 32 + ni * 8 + 2 * t4;
                    const float bx = sm[col], by = sm[col + 1];
                    float c0 = acc[mi][ni][0] + bx;
                    float c1 = acc[mi][ni][1] + by;
                    float c2 = acc[mi][ni][2] + bx;
                    float c3 = acc[mi][ni][3] + by;
                    if (relu) {
                        c0 = fmaxf(c0, 0.f); c1 = fmaxf(c1, 0.f);
                        c2 = fmaxf(c2, 0.f); c3 = fmaxf(c3, 0.f);
                    }
                    *(__half2*)(out + (size_t)r0 * DIM + col) = __floats2half2_rn(c0, c1);
                    *(__half2*)(out + (size_t)(r0 + 8) * DIM + col) = __floats2half2_rn(c2, c3);
                }
            }
        }
        __syncthreads();   // all reads of A done before next build
    }
}

// ---------------------------------------------------------------------------
// Classifier: pooled mean -> relu(P@W1+b1) @ W2 + b2
// ---------------------------------------------------------------------------
__global__ __launch_bounds__(128) void cls_kernel(
    const float* __restrict__ w1, const float* __restrict__ b1,
    const float* __restrict__ w2, const float* __restrict__ b2,
    float* __restrict__ out)
{
    __shared__ float P[128];
    __shared__ float C1[64];
    const int b = blockIdx.x, tid = threadIdx.x;
    P[tid] = g_part[b * DIM + tid] * (1.0f / (float)SEQ);
    __syncthreads();
    if (tid < 64) {
        float a = b1[tid];
        #pragma unroll 8
        for (int k = 0; k < 128; k++) a += P[k] * w1[k * 64 + tid];
        C1[tid] = fmaxf(a, 0.f);
    }
    __syncthreads();
    if (tid < 3) {
        float a = b2[tid];
        #pragma unroll
        for (int k = 0; k < 64; k++) a += C1[k] * w2[k * 3 + tid];
        out[b * 3 + tid] = a;
    }
}

extern "C" void kernel_launch(void* const* d_in, const int* in_sizes, int n_in,
                              void* d_out, int out_size)
{
    const float* x      = (const float*)d_in[0];
    const float* enc_w1 = (const float*)d_in[1];
    const float* enc_b1 = (const float*)d_in[2];
    const float* enc_w2 = (const float*)d_in[3];
    const float* enc_b2 = (const float*)d_in[4];
    const float* gc1_w  = (const float*)d_in[5];
    const float* gc1_b  = (const float*)d_in[6];
    const float* gc2_w  = (const float*)d_in[7];
    const float* gc2_b  = (const float*)d_in[8];
    const float* gc3_w  = (const float*)d_in[9];
    const float* gc3_b  = (const float*)d_in[10];
    const float* cls_w1 = (const float*)d_in[11];
    const float* cls_b1 = (const float*)d_in[12];
    const float* cls_w2 = (const float*)d_in[13];
    const float* cls_b2 = (const float*)d_in[14];
    float* out = (float*)d_out;

    void *p0, *p1, *pwh, *pwl;
    cudaGetSymbolAddress(&p0, g_h0);
    cudaGetSymbolAddress(&p1, g_h1);
    cudaGetSymbolAddress(&pwh, g_Whi);
    cudaGetSymbolAddress(&pwl, g_Wlo);
    __half* h0 = (__half*)p0;
    __half* h1 = (__half*)p1;
    const __half* Whi = (const __half*)pwh;
    const __half* Wlo = (const __half*)pwl;

    const size_t stage_sm = 4096 + 32768 * 3;  // 102400 B -> 2 CTAs/SM
    cudaFuncSetAttribute(stage_kernel, cudaFuncAttributeMaxDynamicSharedMemorySize, (int)stage_sm);
    cudaFuncSetAttribute(stage_kernel, cudaFuncAttributePreferredSharedMemoryCarveout, 100);

    prep_w<<<4, 256>>>(enc_w2, gc1_w, gc2_w, gc3_w);

    stage_kernel<<<GRID, 256, stage_sm>>>(x,  Whi + 0 * DIM * DIM, Wlo + 0 * DIM * DIM, enc_b2, enc_w1, enc_b1, h0, 0);
    stage_kernel<<<GRID, 256, stage_sm>>>(h0, Whi + 1 * DIM * DIM, Wlo + 1 * DIM * DIM, gc1_b,  enc_w1, enc_b1, h1, 1);
    stage_kernel<<<GRID, 256, stage_sm>>>(h1, Whi + 2 * DIM * DIM, Wlo + 2 * DIM * DIM, gc2_b,  enc_w1, enc_b1, h0, 1);
    stage_kernel<<<GRID, 256, stage_sm>>>(h0, Whi + 3 * DIM * DIM, Wlo + 3 * DIM * DIM, gc3_b,  enc_w1, enc_b1, h1, 2);
    cls_kernel<<<NB, 128>>>(cls_w1, cls_b1, cls_w2, cls_b2, out);
}

// round 11
// speedup vs baseline: 1.1807x; 1.1807x over previous
#include <cuda_runtime.h>
#include <cuda_fp16.h>
#include <cstdint>

#define SEQ 2048
#define NB  32
#define DIM 128
#define NTOK (NB*SEQ)
#define TOK 128
#define NTILES (NTOK/TOK)      // 512
#define GRID 296               // 2 CTAs/SM; 216 CTAs do 2 tiles, 80 do 1

// raw ring: 8 chunks of 16 rows (+2 halo) per tile, 2 slots
#define CHUNK_ROWS 16
#define RAW_ROWS   18
#define SLOT_BYTES (RAW_ROWS*256)   // 4608

// ---------------- scratch (no allocations allowed) ----------------
__device__ __align__(16) __half g_h0[NTOK*DIM];
__device__ __align__(16) __half g_h1[NTOK*DIM];
__device__ float g_part[NB*DIM];
// prepared weight images: fp16 hi / scaled-lo(x1024), [n][k], swizzle baked
__device__ __align__(16) __half g_Whi[4][DIM*DIM];
__device__ __align__(16) __half g_Wlo[4][DIM*DIM];

// ---------------- helpers ----------------
__device__ __forceinline__ uint32_t smem_u32(const void* p) {
    uint32_t a;
    asm("{ .reg .u64 t; cvta.to.shared.u64 t, %1; cvt.u32.u64 %0, t; }" : "=r"(a) : "l"(p));
    return a;
}
__device__ __forceinline__ void sts128(uint32_t addr, uint4 v) {
    asm volatile("st.shared.v4.b32 [%0], {%1,%2,%3,%4};" :: "r"(addr), "r"(v.x), "r"(v.y), "r"(v.z), "r"(v.w) : "memory");
}
__device__ __forceinline__ uint4 lds128(uint32_t addr) {
    uint4 v;
    asm volatile("ld.shared.v4.b32 {%0,%1,%2,%3}, [%4];"
        : "=r"(v.x), "=r"(v.y), "=r"(v.z), "=r"(v.w) : "r"(addr));
    return v;
}
__device__ __forceinline__ void cpasync16(uint32_t dst, const void* src) {
    asm volatile("cp.async.cg.shared.global [%0], [%1], 16;" :: "r"(dst), "l"(src) : "memory");
}
#define CP_COMMIT() asm volatile("cp.async.commit_group;" ::: "memory")
#define CP_WAIT0()  asm volatile("cp.async.wait_group 0;" ::: "memory")
#define CP_WAIT1()  asm volatile("cp.async.wait_group 1;" ::: "memory")
#define LDMX4(r, addr) \
    asm volatile("ldmatrix.sync.aligned.m8n8.x4.shared.b16 {%0,%1,%2,%3}, [%4];" \
        : "=r"((r)[0]), "=r"((r)[1]), "=r"((r)[2]), "=r"((r)[3]) : "r"(addr))
__device__ __forceinline__ void mma16816(float* d, const uint32_t* a, const uint32_t* b) {
    asm volatile(
        "mma.sync.aligned.m16n8k16.row.col.f32.f16.f16.f32 "
        "{%0,%1,%2,%3}, {%4,%5,%6,%7}, {%8,%9}, {%0,%1,%2,%3};"
        : "+f"(d[0]), "+f"(d[1]), "+f"(d[2]), "+f"(d[3])
        : "r"(a[0]), "r"(a[1]), "r"(a[2]), "r"(a[3]), "r"(b[0]), "r"(b[1]));
}
// swizzled byte offset inside a [rows][128 fp16] tile: 256B rows, 16B chunks
__device__ __forceinline__ uint32_t tswz(int row, int kchunk) {
    return (uint32_t)(row * 256 + ((kchunk ^ (row & 7)) << 4));
}
__device__ __forceinline__ uint32_t packh(float a, float b) {
    __half2 t = __floats2half2_rn(a, b);
    return *reinterpret_cast<uint32_t*>(&t);
}

// ---------------------------------------------------------------------------
// Weight prep (+ zero pool partials): fp32 [k][n] -> fp16 hi + lo*2^10, [n][k]
// ---------------------------------------------------------------------------
__global__ void prep_w(const float* __restrict__ w0, const float* __restrict__ w1,
                       const float* __restrict__ w2, const float* __restrict__ w3)
{
    const float* ws[4] = {w0, w1, w2, w3};
    const float* w = ws[blockIdx.x];
    __half* bh = g_Whi[blockIdx.x];
    __half* bl = g_Wlo[blockIdx.x];
    if (blockIdx.x == 0) {
        for (int i = threadIdx.x; i < NB * DIM; i += blockDim.x) g_part[i] = 0.f;
    }
    for (int c = threadIdx.x; c < 2048; c += blockDim.x) {
        const int n = c >> 4, kc = c & 15, k0 = kc * 8;
        const int base = n * 128 + ((kc ^ (n & 7)) << 3);
        #pragma unroll
        for (int j = 0; j < 8; j++) {
            const float v = w[(k0 + j) * DIM + n];
            const __half hi = __float2half_rn(v);
            bh[base + j] = hi;
            bl[base + j] = __float2half_rn((v - __half2float(hi)) * 1024.0f);
        }
    }
}

// ---------------------------------------------------------------------------
// Persistent stage kernel: TOK=128, 2 CTAs/SM (folded acc, regs<=128).
// Raw activations streamed via 2-slot cp.async chunk ring into A tile.
// mode 0 = encoder, mode 1 = gc (store), mode 2 = gc + fused mean-pool
// ---------------------------------------------------------------------------
__global__ __launch_bounds__(256, 2)
void stage_kernel(const void* __restrict__ in_v,
                  const __half* __restrict__ Whi_g,
                  const __half* __restrict__ Wlo_g,
                  const float* __restrict__ bias,
                  const float* __restrict__ w1, const float* __restrict__ b1,
                  __half* __restrict__ out, int mode)
{
    extern __shared__ float sm[];
    const int tid = threadIdx.x;
    const int wid = tid >> 5, lid = tid & 31;
    const uint32_t smb = smem_u32(sm);
    const uint32_t AS   = smb + 1024;        // 32KB (128 x 256B)
    const uint32_t BhS  = AS + 32768;        // 32KB
    const uint32_t BlS  = BhS + 32768;       // 32KB
    const uint32_t ring = BlS + 32768;       // 2 x 4608B
    // mode0 header (w1[768]+b1[128]) lives in the ring area (unused in mode0)
    float* hdr = (float*)((char*)sm + (ring - smb));

    // ---- prologue: B hi/lo images (one cp.async group) + headers ----
    {
        const char* sh = (const char*)Whi_g;
        const char* sl = (const char*)Wlo_g;
        #pragma unroll
        for (int it = 0; it < 8; it++) {
            const int i = tid + it * 256;
            cpasync16(BhS + i * 16, sh + i * 16);
            cpasync16(BlS + i * 16, sl + i * 16);
        }
        CP_COMMIT();
    }
    if (tid < 128) sm[tid] = bias[tid];
    if (mode == 0) {
        for (int i = tid; i < 768; i += 256) hdr[i] = w1[i];
        if (tid < 128) hdr[768 + tid] = b1[tid];
    }
    CP_WAIT0();
    __syncthreads();

    const int wm = wid & 1, wn = wid >> 1;         // warp grid 2m x 4n
    const int g = lid >> 2, t4 = lid & 3;
    const int arowl = ((lid >> 3) & 1) * 8 + (lid & 7);
    const int akcl  = lid >> 4;
    const int browl = (lid >> 4) * 8 + (lid & 7);
    const int bkcl  = (lid >> 3) & 1;
    const __half* hin = (const __half*)in_v;

    for (int tile = blockIdx.x; tile < NTILES; tile += GRID) {
        const int token0 = tile * TOK;
        const int s0 = token0 & (SEQ - 1);
        const int bb = token0 - s0;

        // ---- build A fp16 tile (128 x 128), swizzled ----
        if (mode != 0) {
            // chunk fetch helper pattern: chunk i covers seq rows s0+16i-1 .. s0+16i+16
            // issue chunks 0 and 1
            #pragma unroll
            for (int ic = 0; ic < 2; ic++) {
                const uint32_t slot = ring + ic * SLOT_BYTES;
                for (int j = tid; j < RAW_ROWS * 16; j += 256) {
                    const int lr = j >> 4, c = j & 15;
                    const int s = s0 + ic * CHUNK_ROWS - 1 + lr;
                    const uint32_t dst = slot + tswz(lr, c);
                    if (s >= 0 && s < SEQ) cpasync16(dst, hin + (size_t)(bb + s) * DIM + c * 8);
                    else                   sts128(dst, make_uint4(0, 0, 0, 0));
                }
                CP_COMMIT();
            }
            const int o = tid >> 4, c16 = tid & 15;   // 16 rows x 16 cols
            #pragma unroll
            for (int i = 0; i < 8; i++) {
                CP_WAIT1();          // chunk i landed (chunk i+1 may be pending)
                __syncthreads();
                const uint32_t slot = ring + (i & 1) * SLOT_BYTES;
                const int r = i * CHUNK_ROWS + o;
                const int s = s0 + r;
                const float scf = (s == 0 || s == SEQ - 1) ? 0.5f : (1.0f / 3.0f);
                const __half2 sc = __float2half2_rn(scf);
                const uint4 u0 = lds128(slot + tswz(o,     c16));
                const uint4 u1 = lds128(slot + tswz(o + 1, c16));
                const uint4 u2 = lds128(slot + tswz(o + 2, c16));
                uint4 ov;
                const uint32_t* p0 = &u0.x;
                const uint32_t* p1 = &u1.x;
                const uint32_t* p2 = &u2.x;
                uint32_t* po = &ov.x;
                #pragma unroll
                for (int wd = 0; wd < 4; wd++) {
                    __half2 a = *(const __half2*)&p0[wd];
                    __half2 b = *(const __half2*)&p1[wd];
                    __half2 cc = *(const __half2*)&p2[wd];
                    __half2 sv = __hmul2(__hadd2(__hadd2(a, b), cc), sc);
                    po[wd] = *reinterpret_cast<uint32_t*>(&sv);
                }
                sts128(AS + tswz(r, c16), ov);
                __syncthreads();     // slot readers done before reissue
                if (i + 2 < 8) {
                    const uint32_t sl2 = ring + (i & 1) * SLOT_BYTES;
                    for (int j = tid; j < RAW_ROWS * 16; j += 256) {
                        const int lr = j >> 4, c = j & 15;
                        const int s2 = s0 + (i + 2) * CHUNK_ROWS - 1 + lr;
                        const uint32_t dst = sl2 + tswz(lr, c);
                        if (s2 >= 0 && s2 < SEQ) cpasync16(dst, hin + (size_t)(bb + s2) * DIM + c * 8);
                        else                     sts128(dst, make_uint4(0, 0, 0, 0));
                    }
                }
                CP_COMMIT();         // keep group count advancing (may be empty)
            }
            __syncthreads();         // A complete
        } else {
            const float* x = (const float*)in_v;
            const int r = tid >> 1, q = tid & 1;
            float xv[6];
            const float* xr = x + (size_t)(token0 + r) * 6;
            #pragma unroll
            for (int k = 0; k < 6; k++) xv[k] = xr[k];
            #pragma unroll
            for (int ch = 0; ch < 8; ch++) {
                const int c = q * 8 + ch;
                const int k0 = c * 8;
                uint4 o;
                uint32_t* po = &o.x;
                #pragma unroll
                for (int wd = 0; wd < 4; wd++) {
                    float v0, v1;
                    {
                        const int cc = k0 + wd * 2;
                        float a = hdr[768 + cc];
                        #pragma unroll
                        for (int k = 0; k < 6; k++) a += xv[k] * hdr[k * 128 + cc];
                        v0 = fmaxf(a, 0.f);
                    }
                    {
                        const int cc = k0 + wd * 2 + 1;
                        float a = hdr[768 + cc];
                        #pragma unroll
                        for (int k = 0; k < 6; k++) a += xv[k] * hdr[k * 128 + cc];
                        v1 = fmaxf(a, 0.f);
                    }
                    po[wd] = packh(v0, v1);
                }
                sts128(AS + tswz(r, c), o);
            }
            __syncthreads();
        }

        // ---- folded 2-pass GEMM: acc = (A@Wlo)/1024 + A@Whi ----
        float acc[4][4][4];
        #pragma unroll
        for (int mi = 0; mi < 4; mi++)
            #pragma unroll
            for (int ni = 0; ni < 4; ni++)
                #pragma unroll
                for (int j = 0; j < 4; j++) acc[mi][ni][j] = 0.f;

        // pass 1: lo
        #pragma unroll
        for (int ks = 0; ks < 8; ks++) {
            uint32_t ah[4][4];
            #pragma unroll
            for (int mi = 0; mi < 4; mi++)
                LDMX4(ah[mi], AS + tswz(wm * 64 + mi * 16 + arowl, ks * 2 + akcl));
            #pragma unroll
            for (int p = 0; p < 2; p++) {
                uint32_t bf[4];
                LDMX4(bf, BlS + tswz(wn * 32 + p * 16 + browl, ks * 2 + bkcl));
                #pragma unroll
                for (int hn = 0; hn < 2; hn++)
                    #pragma unroll
                    for (int mi = 0; mi < 4; mi++)
                        mma16816(acc[mi][p * 2 + hn], ah[mi], &bf[hn * 2]);
            }
        }
        #pragma unroll
        for (int mi = 0; mi < 4; mi++)
            #pragma unroll
            for (int ni = 0; ni < 4; ni++)
                #pragma unroll
                for (int j = 0; j < 4; j++) acc[mi][ni][j] *= (1.0f / 1024.0f);
        // pass 2: hi
        #pragma unroll
        for (int ks = 0; ks < 8; ks++) {
            uint32_t ah[4][4];
            #pragma unroll
            for (int mi = 0; mi < 4; mi++)
                LDMX4(ah[mi], AS + tswz(wm * 64 + mi * 16 + arowl, ks * 2 + akcl));
            #pragma unroll
            for (int p = 0; p < 2; p++) {
                uint32_t bf[4];
                LDMX4(bf, BhS + tswz(wn * 32 + p * 16 + browl, ks * 2 + bkcl));
                #pragma unroll
                for (int hn = 0; hn < 2; hn++)
                    #pragma unroll
                    for (int mi = 0; mi < 4; mi++)
                        mma16816(acc[mi][p * 2 + hn], ah[mi], &bf[hn * 2]);
            }
        }

        // ---- epilogue ----
        if (mode == 2) {
            const int b = token0 >> 11;
            #pragma unroll
            for (int ni = 0; ni < 4; ni++) {
                const int col = wn * 32 + ni * 8 + 2 * t4;
                const float bx = sm[col], by = sm[col + 1];
                float sx = 0.f, sy = 0.f;
                #pragma unroll
                for (int mi = 0; mi < 4; mi++) {
                    sx += fmaxf(acc[mi][ni][0] + bx, 0.f) + fmaxf(acc[mi][ni][2] + bx, 0.f);
                    sy += fmaxf(acc[mi][ni][1] + by, 0.f) + fmaxf(acc[mi][ni][3] + by, 0.f);
                }
                sx += __shfl_xor_sync(0xFFFFFFFFu, sx, 16);
                sy += __shfl_xor_sync(0xFFFFFFFFu, sy, 16);
                sx += __shfl_xor_sync(0xFFFFFFFFu, sx, 8);
                sy += __shfl_xor_sync(0xFFFFFFFFu, sy, 8);
                sx += __shfl_xor_sync(0xFFFFFFFFu, sx, 4);
                sy += __shfl_xor_sync(0xFFFFFFFFu, sy, 4);
                if (g == 0) {
                    atomicAdd(&g_part[b * DIM + col], sx);
                    atomicAdd(&g_part[b * DIM + col + 1], sy);
                }
            }
        } else {
            const bool relu = (mode == 1);
            #pragma unroll
            for (int mi = 0; mi < 4; mi++) {
                const int r0 = token0 + wm * 64 + mi * 16 + g;
                #pragma unroll
                for (int ni = 0; ni < 4; ni++) {
                    const int col = wn * 32 + ni * 8 + 2 * t4;
                    const float bx = sm[col], by = sm[col + 1];
                    float c0 = acc[mi][ni][0] + bx;
                    float c1 = acc[mi][ni][1] + by;
                    float c2 = acc[mi][ni][2] + bx;
                    float c3 = acc[mi][ni][3] + by;
                    if (relu) {
                        c0 = fmaxf(c0, 0.f); c1 = fmaxf(c1, 0.f);
                        c2 = fmaxf(c2, 0.f); c3 = fmaxf(c3, 0.f);
                    }
                    *(__half2*)(out + (size_t)r0 * DIM + col) = __floats2half2_rn(c0, c1);
                    *(__half2*)(out + (size_t)(r0 + 8) * DIM + col) = __floats2half2_rn(c2, c3);
                }
            }
        }
        __syncthreads();   // A readers done before next tile's build
    }
}

// ---------------------------------------------------------------------------
// Classifier: pooled mean -> relu(P@W1+b1) @ W2 + b2
// ---------------------------------------------------------------------------
__global__ __launch_bounds__(128) void cls_kernel(
    const float* __restrict__ w1, const float* __restrict__ b1,
    const float* __restrict__ w2, const float* __restrict__ b2,
    float* __restrict__ out)
{
    __shared__ float P[128];
    __shared__ float C1[64];
    const int b = blockIdx.x, tid = threadIdx.x;
    P[tid] = g_part[b * DIM + tid] * (1.0f / (float)SEQ);
    __syncthreads();
    if (tid < 64) {
        float a = b1[tid];
        #pragma unroll 8
        for (int k = 0; k < 128; k++) a += P[k] * w1[k * 64 + tid];
        C1[tid] = fmaxf(a, 0.f);
    }
    __syncthreads();
    if (tid < 3) {
        float a = b2[tid];
        #pragma unroll
        for (int k = 0; k < 64; k++) a += C1[k] * w2[k * 3 + tid];
        out[b * 3 + tid] = a;
    }
}

extern "C" void kernel_launch(void* const* d_in, const int* in_sizes, int n_in,
                              void* d_out, int out_size)
{
    const float* x      = (const float*)d_in[0];
    const float* enc_w1 = (const float*)d_in[1];
    const float* enc_b1 = (const float*)d_in[2];
    const float* enc_w2 = (const float*)d_in[3];
    const float* enc_b2 = (const float*)d_in[4];
    const float* gc1_w  = (const float*)d_in[5];
    const float* gc1_b  = (const float*)d_in[6];
    const float* gc2_w  = (const float*)d_in[7];
    const float* gc2_b  = (const float*)d_in[8];
    const float* gc3_w  = (const float*)d_in[9];
    const float* gc3_b  = (const float*)d_in[10];
    const float* cls_w1 = (const float*)d_in[11];
    const float* cls_b1 = (const float*)d_in[12];
    const float* cls_w2 = (const float*)d_in[13];
    const float* cls_b2 = (const float*)d_in[14];
    float* out = (float*)d_out;

    void *p0, *p1, *pwh, *pwl;
    cudaGetSymbolAddress(&p0, g_h0);
    cudaGetSymbolAddress(&p1, g_h1);
    cudaGetSymbolAddress(&pwh, g_Whi);
    cudaGetSymbolAddress(&pwl, g_Wlo);
    __half* h0 = (__half*)p0;
    __half* h1 = (__half*)p1;
    const __half* Whi = (const __half*)pwh;
    const __half* Wlo = (const __half*)pwl;

    const size_t stage_sm = 1024 + 32768 * 3 + 2 * SLOT_BYTES;  // 108544 B -> 2 CTAs/SM
    cudaFuncSetAttribute(stage_kernel, cudaFuncAttributeMaxDynamicSharedMemorySize, (int)stage_sm);
    cudaFuncSetAttribute(stage_kernel, cudaFuncAttributePreferredSharedMemoryCarveout, 100);

    prep_w<<<4, 256>>>(enc_w2, gc1_w, gc2_w, gc3_w);

    stage_kernel<<<GRID, 256, stage_sm>>>(x,  Whi + 0 * DIM * DIM, Wlo + 0 * DIM * DIM, enc_b2, enc_w1, enc_b1, h0, 0);
    stage_kernel<<<GRID, 256, stage_sm>>>(h0, Whi + 1 * DIM * DIM, Wlo + 1 * DIM * DIM, gc1_b,  enc_w1, enc_b1, h1, 1);
    stage_kernel<<<GRID, 256, stage_sm>>>(h1, Whi + 2 * DIM * DIM, Wlo + 2 * DIM * DIM, gc2_b,  enc_w1, enc_b1, h0, 1);
    stage_kernel<<<GRID, 256, stage_sm>>>(h0, Whi + 3 * DIM * DIM, Wlo + 3 * DIM * DIM, gc3_b,  enc_w1, enc_b1, h1, 2);
    cls_kernel<<<NB, 128>>>(cls_w1, cls_b1, cls_w2, cls_b2, out);
}

// round 12
// speedup vs baseline: 2.3031x; 1.9507x over previous
#include <cuda_runtime.h>
#include <cuda_fp16.h>
#include <cstdint>

#define SEQ 2048
#define NB  32
#define DIM 128
#define NTOK (NB*SEQ)
#define TOK 128
#define NTILES (NTOK/TOK)      // 512
#define GRID 128               // all co-resident (1 CTA/SM), 4 tiles each

// ---------------- scratch (no allocations allowed) ----------------
__device__ __align__(16) __half g_h0[NTOK*DIM];
__device__ __align__(16) __half g_h1[NTOK*DIM];
__device__ float g_part[NB*DIM];
__device__ __align__(16) __half g_Whi[4][DIM*DIM];
__device__ __align__(16) __half g_Wlo[4][DIM*DIM];
__device__ unsigned g_ctr;     // monotonic grid-barrier counter (replay-safe)

// ---------------- helpers ----------------
__device__ __forceinline__ uint32_t smem_u32(const void* p) {
    uint32_t a;
    asm("{ .reg .u64 t; cvta.to.shared.u64 t, %1; cvt.u32.u64 %0, t; }" : "=r"(a) : "l"(p));
    return a;
}
__device__ __forceinline__ void sts128(uint32_t addr, uint4 v) {
    asm volatile("st.shared.v4.b32 [%0], {%1,%2,%3,%4};" :: "r"(addr), "r"(v.x), "r"(v.y), "r"(v.z), "r"(v.w) : "memory");
}
__device__ __forceinline__ uint4 lds128(uint32_t addr) {
    uint4 v;
    asm volatile("ld.shared.v4.b32 {%0,%1,%2,%3}, [%4];"
        : "=r"(v.x), "=r"(v.y), "=r"(v.z), "=r"(v.w) : "r"(addr));
    return v;
}
__device__ __forceinline__ void cpasync16(uint32_t dst, const void* src) {
    asm volatile("cp.async.cg.shared.global [%0], [%1], 16;" :: "r"(dst), "l"(src) : "memory");
}
#define CP_COMMIT() asm volatile("cp.async.commit_group;" ::: "memory")
#define CP_WAIT0()  asm volatile("cp.async.wait_group 0;" ::: "memory")
#define LDMX4(r, addr) \
    asm volatile("ldmatrix.sync.aligned.m8n8.x4.shared.b16 {%0,%1,%2,%3}, [%4];" \
        : "=r"((r)[0]), "=r"((r)[1]), "=r"((r)[2]), "=r"((r)[3]) : "r"(addr))
__device__ __forceinline__ void mma16816(float* d, const uint32_t* a, const uint32_t* b) {
    asm volatile(
        "mma.sync.aligned.m16n8k16.row.col.f32.f16.f16.f32 "
        "{%0,%1,%2,%3}, {%4,%5,%6,%7}, {%8,%9}, {%0,%1,%2,%3};"
        : "+f"(d[0]), "+f"(d[1]), "+f"(d[2]), "+f"(d[3])
        : "r"(a[0]), "r"(a[1]), "r"(a[2]), "r"(a[3]), "r"(b[0]), "r"(b[1]));
}
__device__ __forceinline__ uint32_t tswz(int row, int kchunk) {
    return (uint32_t)(row * 256 + ((kchunk ^ (row & 7)) << 4));
}
__device__ __forceinline__ uint32_t packh(float a, float b) {
    __half2 t = __floats2half2_rn(a, b);
    return *reinterpret_cast<uint32_t*>(&t);
}

// replay-safe grid barrier: monotonic counter, release->acquire via threadfence
__device__ __forceinline__ void grid_barrier() {
    __syncthreads();
    if (threadIdx.x == 0) {
        __threadfence();
        const unsigned t = atomicAdd(&g_ctr, 1u) + 1u;
        const unsigned target = ((t + GRID - 1u) / GRID) * GRID;
        while (atomicAdd(&g_ctr, 0u) < target) { __nanosleep(64); }
        __threadfence();
    }
    __syncthreads();
}

// ---------------------------------------------------------------------------
// ONE persistent kernel: weight prep -> 4 GEMM stages -> classifier
// ---------------------------------------------------------------------------
__global__ __launch_bounds__(256, 1)
void mega_kernel(const float* __restrict__ x,
                 const float* __restrict__ enc_w1, const float* __restrict__ enc_b1,
                 const float* __restrict__ enc_w2, const float* __restrict__ enc_b2,
                 const float* __restrict__ gc1_w,  const float* __restrict__ gc1_b,
                 const float* __restrict__ gc2_w,  const float* __restrict__ gc2_b,
                 const float* __restrict__ gc3_w,  const float* __restrict__ gc3_b,
                 const float* __restrict__ cls_w1, const float* __restrict__ cls_b1,
                 const float* __restrict__ cls_w2, const float* __restrict__ cls_b2,
                 float* __restrict__ out)
{
    extern __shared__ float sm[];
    const int tid = threadIdx.x;
    const int wid = tid >> 5, lid = tid & 31;
    const uint32_t smb = smem_u32(sm);
    const uint32_t A0S  = smb + 4096;        // 32KB (128 x 256B)
    const uint32_t A1S  = A0S + 32768;       // 32KB
    const uint32_t BhS  = A1S + 32768;       // 32KB
    const uint32_t BlS  = BhS + 32768;       // 32KB
    const uint32_t rawS = BlS + 32768;       // 33.3KB (130 x 256B)

    // ================= phase 0: weight prep + zero pool =================
    {
        const int gid = blockIdx.x * 256 + tid;
        if (gid < 4 * 2048) {
            const float* ws[4] = {enc_w2, gc1_w, gc2_w, gc3_w};
            const int layer = gid >> 11, c = gid & 2047;
            const float* w = ws[layer];
            __half* bh = g_Whi[layer];
            __half* bl = g_Wlo[layer];
            const int n = c >> 4, kc = c & 15, k0 = kc * 8;
            const int base = n * 128 + ((kc ^ (n & 7)) << 3);
            #pragma unroll
            for (int j = 0; j < 8; j++) {
                const float v = w[(k0 + j) * DIM + n];
                const __half hi = __float2half_rn(v);
                bh[base + j] = hi;
                bl[base + j] = __float2half_rn((v - __half2float(hi)) * 1024.0f);
            }
        }
        if (gid < NB * DIM) g_part[gid] = 0.f;
    }
    grid_barrier();

    // lane constants
    const int wm = wid & 1, wn = wid >> 1;         // warp grid 2m x 4n
    const int g = lid >> 2, t4 = lid & 3;
    const int arowl = ((lid >> 3) & 1) * 8 + (lid & 7);
    const int akcl  = lid >> 4;
    const int browl = (lid >> 4) * 8 + (lid & 7);
    const int bkcl  = (lid >> 3) & 1;
    const float INV = 1.0f / 1024.0f;
    // gc-build mapping: thread -> 4 rows x 2 chunks (6-row window, 1.5x reads)
    const int brg = tid >> 3, bcc = (tid & 7) * 2;

    // ================= phases 1..4: the four GEMM stages =================
    #pragma unroll 1
    for (int s = 0; s < 4; s++) {
        const int mode = (s == 0) ? 0 : ((s == 3) ? 2 : 1);
        const __half* Whi_g = g_Whi[s];
        const __half* Wlo_g = g_Wlo[s];
        const float* bias = (s == 0) ? enc_b2 : ((s == 1) ? gc1_b : ((s == 2) ? gc2_b : gc3_b));
        const __half* hin = (s == 1) ? g_h0 : ((s == 2) ? g_h1 : g_h0);
        __half* outp = (s == 0) ? g_h0 : ((s == 1) ? g_h1 : ((s == 2) ? g_h0 : g_h1));

        auto issue_raw = [&](int tile) {
            const int tok0 = tile * TOK, s0 = tok0 & (SEQ - 1), bb = tok0 - s0;
            for (int i = tid; i < 130 * 16; i += 256) {
                const int row = i >> 4, c = i & 15;
                const int sq = s0 - 1 + row;
                const uint32_t dst = rawS + tswz(row, c);
                if (sq >= 0 && sq < SEQ) cpasync16(dst, hin + (size_t)(bb + sq) * DIM + c * 8);
                else                     sts128(dst, make_uint4(0, 0, 0, 0));
            }
        };
        auto build_A = [&](int tile, uint32_t AS) {
            const int token0 = tile * TOK;
            if (mode != 0) {
                const int s0 = token0 & (SEQ - 1);
                #pragma unroll
                for (int ci = 0; ci < 2; ci++) {
                    const int c = bcc + ci;
                    uint4 u[6];
                    #pragma unroll
                    for (int j = 0; j < 6; j++) u[j] = lds128(rawS + tswz(4 * brg + j, c));
                    #pragma unroll
                    for (int k = 0; k < 4; k++) {
                        const int row = 4 * brg + k;
                        const int sq = s0 + row;
                        const float scf = (sq == 0 || sq == SEQ - 1) ? 0.5f : (1.0f / 3.0f);
                        const __half2 sc = __float2half2_rn(scf);
                        uint4 ov;
                        const uint32_t* p0 = &u[k].x;
                        const uint32_t* p1 = &u[k + 1].x;
                        const uint32_t* p2 = &u[k + 2].x;
                        uint32_t* po = &ov.x;
                        #pragma unroll
                        for (int wd = 0; wd < 4; wd++) {
                            __half2 a = *(const __half2*)&p0[wd];
                            __half2 b = *(const __half2*)&p1[wd];
                            __half2 cc = *(const __half2*)&p2[wd];
                            __half2 sv = __hmul2(__hadd2(__hadd2(a, b), cc), sc);
                            po[wd] = *reinterpret_cast<uint32_t*>(&sv);
                        }
                        sts128(AS + tswz(row, c), ov);
                    }
                }
            } else {
                const int r = tid >> 1, q = tid & 1;
                float xv[6];
                const float* xr = x + (size_t)(token0 + r) * 6;
                #pragma unroll
                for (int k = 0; k < 6; k++) xv[k] = xr[k];
                #pragma unroll
                for (int ch = 0; ch < 8; ch++) {
                    const int c = q * 8 + ch;
                    const int k0 = c * 8;
                    uint4 o;
                    uint32_t* po = &o.x;
                    #pragma unroll
                    for (int wd = 0; wd < 4; wd++) {
                        float v0, v1;
                        {
                            const int cc = k0 + wd * 2;
                            float a = sm[896 + cc];
                            #pragma unroll
                            for (int k = 0; k < 6; k++) a += xv[k] * sm[128 + k * 128 + cc];
                            v0 = fmaxf(a, 0.f);
                        }
                        {
                            const int cc = k0 + wd * 2 + 1;
                            float a = sm[896 + cc];
                            #pragma unroll
                            for (int k = 0; k < 6; k++) a += xv[k] * sm[128 + k * 128 + cc];
                            v1 = fmaxf(a, 0.f);
                        }
                        po[wd] = packh(v0, v1);
                    }
                    sts128(AS + tswz(r, c), o);
                }
            }
        };

        // ---- stage prologue: B images + first raw tile + headers ----
        {
            const char* sh = (const char*)Whi_g;
            const char* sl = (const char*)Wlo_g;
            #pragma unroll
            for (int it = 0; it < 8; it++) {
                const int i = tid + it * 256;
                cpasync16(BhS + i * 16, sh + i * 16);
                cpasync16(BlS + i * 16, sl + i * 16);
            }
        }
        if (mode != 0) issue_raw(blockIdx.x);
        CP_COMMIT();
        if (tid < 128) sm[tid] = bias[tid];
        if (mode == 0) {
            for (int i = tid; i < 768; i += 256) sm[128 + i] = enc_w1[i];
            if (tid < 128) sm[896 + tid] = enc_b1[tid];
        }
        CP_WAIT0();
        __syncthreads();
        build_A(blockIdx.x, A0S);

        int ph = 0;
        for (int tile = blockIdx.x; tile < NTILES; tile += GRID, ph ^= 1) {
            const int token0 = tile * TOK;
            const int tnext = tile + GRID;

            __syncthreads();     // A(tile) visible; raw buffer free of readers

            if (mode != 0 && tnext < NTILES) issue_raw(tnext);
            CP_COMMIT();

            const uint32_t AS = ph ? A1S : A0S;

            // ---- warp-level 2-product GEMM: warp tile 64 x 32 ----
            float acc1[4][4][4], acc2[4][4][4];
            #pragma unroll
            for (int mi = 0; mi < 4; mi++)
                #pragma unroll
                for (int ni = 0; ni < 4; ni++)
                    #pragma unroll
                    for (int j = 0; j < 4; j++) { acc1[mi][ni][j] = 0.f; acc2[mi][ni][j] = 0.f; }

            #pragma unroll
            for (int ks = 0; ks < 8; ks++) {
                uint32_t ah[4][4];
                #pragma unroll
                for (int mi = 0; mi < 4; mi++)
                    LDMX4(ah[mi], AS + tswz(wm * 64 + mi * 16 + arowl, ks * 2 + akcl));
                #pragma unroll
                for (int p = 0; p < 2; p++) {
                    const uint32_t boff = tswz(wn * 32 + p * 16 + browl, ks * 2 + bkcl);
                    uint32_t bh[4], bl[4];
                    LDMX4(bh, BhS + boff);
                    LDMX4(bl, BlS + boff);
                    #pragma unroll
                    for (int hn = 0; hn < 2; hn++) {
                        const int ni = p * 2 + hn;
                        #pragma unroll
                        for (int mi = 0; mi < 4; mi++) {
                            mma16816(acc1[mi][ni], ah[mi], &bh[hn * 2]);
                            mma16816(acc2[mi][ni], ah[mi], &bl[hn * 2]);
                        }
                    }
                }
            }

            // ---- epilogue ----
            if (mode == 2) {
                const int b = token0 >> 11;
                #pragma unroll
                for (int ni = 0; ni < 4; ni++) {
                    const int col = wn * 32 + ni * 8 + 2 * t4;
                    const float bx = sm[col], by = sm[col + 1];
                    float sx = 0.f, sy = 0.f;
                    #pragma unroll
                    for (int mi = 0; mi < 4; mi++) {
                        sx += fmaxf(acc1[mi][ni][0] + acc2[mi][ni][0] * INV + bx, 0.f)
                            + fmaxf(acc1[mi][ni][2] + acc2[mi][ni][2] * INV + bx, 0.f);
                        sy += fmaxf(acc1[mi][ni][1] + acc2[mi][ni][1] * INV + by, 0.f)
                            + fmaxf(acc1[mi][ni][3] + acc2[mi][ni][3] * INV + by, 0.f);
                    }
                    sx += __shfl_xor_sync(0xFFFFFFFFu, sx, 16);
                    sy += __shfl_xor_sync(0xFFFFFFFFu, sy, 16);
                    sx += __shfl_xor_sync(0xFFFFFFFFu, sx, 8);
                    sy += __shfl_xor_sync(0xFFFFFFFFu, sy, 8);
                    sx += __shfl_xor_sync(0xFFFFFFFFu, sx, 4);
                    sy += __shfl_xor_sync(0xFFFFFFFFu, sy, 4);
                    if (g == 0) {
                        atomicAdd(&g_part[b * DIM + col], sx);
                        atomicAdd(&g_part[b * DIM + col + 1], sy);
                    }
                }
            } else {
                const bool relu = (mode == 1);
                #pragma unroll
                for (int mi = 0; mi < 4; mi++) {
                    const int r0 = token0 + wm * 64 + mi * 16 + g;
                    #pragma unroll
                    for (int ni = 0; ni < 4; ni++) {
                        const int col = wn * 32 + ni * 8 + 2 * t4;
                        const float bx = sm[col], by = sm[col + 1];
                        float c0 = acc1[mi][ni][0] + acc2[mi][ni][0] * INV + bx;
                        float c1 = acc1[mi][ni][1] + acc2[mi][ni][1] * INV + by;
                        float c2 = acc1[mi][ni][2] + acc2[mi][ni][2] * INV + bx;
                        float c3 = acc1[mi][ni][3] + acc2[mi][ni][3] * INV + by;
                        if (relu) {
                            c0 = fmaxf(c0, 0.f); c1 = fmaxf(c1, 0.f);
                            c2 = fmaxf(c2, 0.f); c3 = fmaxf(c3, 0.f);
                        }
                        *(__half2*)(outp + (size_t)r0 * DIM + col) = __floats2half2_rn(c0, c1);
                        *(__half2*)(outp + (size_t)(r0 + 8) * DIM + col) = __floats2half2_rn(c2, c3);
                    }
                }
            }

            if (tnext < NTILES) {
                CP_WAIT0();
                build_A(tnext, ph ? A0S : A1S);
            }
        }
        grid_barrier();   // stage complete chip-wide before next stage reads
    }

    // ================= phase 5: classifier (CTAs 0..31) =================
    if (blockIdx.x < NB) {
        const int b = blockIdx.x;
        float* P  = sm;         // reuse smem
        float* C1 = sm + 128;
        if (tid < 128) P[tid] = __ldcg(&g_part[b * DIM + tid]) * (1.0f / (float)SEQ);
        __syncthreads();
        if (tid < 64) {
            float a = cls_b1[tid];
            #pragma unroll 8
            for (int k = 0; k < 128; k++) a += P[k] * cls_w1[k * 64 + tid];
            C1[tid] = fmaxf(a, 0.f);
        }
        __syncthreads();
        if (tid < 3) {
            float a = cls_b2[tid];
            #pragma unroll
            for (int k = 0; k < 64; k++) a += C1[k] * cls_w2[k * 3 + tid];
            out[b * 3 + tid] = a;
        }
    }
}

extern "C" void kernel_launch(void* const* d_in, const int* in_sizes, int n_in,
                              void* d_out, int out_size)
{
    const float* x      = (const float*)d_in[0];
    const float* enc_w1 = (const float*)d_in[1];
    const float* enc_b1 = (const float*)d_in[2];
    const float* enc_w2 = (const float*)d_in[3];
    const float* enc_b2 = (const float*)d_in[4];
    const float* gc1_w  = (const float*)d_in[5];
    const float* gc1_b  = (const float*)d_in[6];
    const float* gc2_w  = (const float*)d_in[7];
    const float* gc2_b  = (const float*)d_in[8];
    const float* gc3_w  = (const float*)d_in[9];
    const float* gc3_b  = (const float*)d_in[10];
    const float* cls_w1 = (const float*)d_in[11];
    const float* cls_b1 = (const float*)d_in[12];
    const float* cls_w2 = (const float*)d_in[13];
    const float* cls_b2 = (const float*)d_in[14];
    float* out = (float*)d_out;

    const size_t mega_sm = 4096 + 32768 * 4 + 130 * 256;  // 168448 B
    cudaFuncSetAttribute(mega_kernel, cudaFuncAttributeMaxDynamicSharedMemorySize, (int)mega_sm);
    cudaFuncSetAttribute(mega_kernel, cudaFuncAttributePreferredSharedMemoryCarveout, 100);

    mega_kernel<<<GRID, 256, mega_sm>>>(x, enc_w1, enc_b1, enc_w2, enc_b2,
                                        gc1_w, gc1_b, gc2_w, gc2_b, gc3_w, gc3_b,
                                        cls_w1, cls_b1, cls_w2, cls_b2, out);
}